// round 5
// baseline (speedup 1.0000x reference)
#include <cuda_runtime.h>
#include <math.h>

// Problem constants
#define HH 128
#define WW 128
#define HW 16384        // 128*128
#define NB 4            // batch
#define NC 64           // in channels
#define NO 64           // out channels
#define NMC 192         // 3 masks * 64 channels
#define NIC2 256        // 4 dilations * 64

typedef unsigned long long ull;

// Scratch (device globals: allocation-free per harness rules)
__device__ float g_xm[NB * NMC * HW];        // 50.3 MB: x * mask, fused (m,c) channels
__device__ float g_cat[NB * NIC2 * HW];      // 67.1 MB: concatenated branch outputs
__device__ float g_wbr[NB * NMC * 9 * 64];   // packed branch weights [b][mc][tap][o]
__device__ float g_wout[NIC2 * 9 * 64];      // packed fuse weights  [ic][tap][o]

// Packed dual-fp32 FMA (sm_103a FFMA2; ptxas never auto-fuses this)
#define FMA2(acc, a, b) \
    asm("fma.rn.f32x2 %0, %1, %2, %0;" : "+l"(acc) : "l"(a), "l"(b))

// 4-byte cp.async with zero-fill when sz==0 (OOB padding)
#define CP4(saddr, gptr, sz) \
    asm volatile("cp.async.ca.shared.global [%0], [%1], 4, %2;" \
                 :: "r"(saddr), "l"(gptr), "r"(sz))
#define CP_COMMIT() asm volatile("cp.async.commit_group;")
#define CP_WAIT0()  asm volatile("cp.async.wait_group 0;")

// ---------------------------------------------------------------------------
// Weight prepack: branch weights kernel[b,m,o,c,kh,kw] -> [b][mc=m*64+c][tap][o]
//                 fuse weights conv_out_w[o,ic,kh,kw]  -> [ic][tap][o]
// ---------------------------------------------------------------------------
__global__ void prep_w_kernel(const float* __restrict__ kern,
                              const float* __restrict__ cow)
{
    int i = blockIdx.x * 256 + threadIdx.x;
    if (i < NB * NMC * 9 * 64) {
        int o   = i & 63;
        int rt  = i >> 6;        // r*9 + tap
        int tap = rt % 9;
        int r   = rt / 9;        // b*192 + mc
        int b   = r / NMC;
        int mc  = r - b * NMC;
        int m   = mc >> 6;
        int c   = mc & 63;
        g_wbr[i] = kern[(((b * 3 + m) * 64 + o) * 64 + c) * 9 + tap];
    }
    if (i < NIC2 * 9 * 64) {
        int o   = i & 63;
        int rt  = i >> 6;
        int tap = rt % 9;
        int ic  = rt / 9;
        g_wout[i] = cow[(o * NIC2 + ic) * 9 + tap];
    }
}

// ---------------------------------------------------------------------------
// Stage 1: mask conv (3x3, pad 1) + channel softmax over 3. One thread/pixel.
// ---------------------------------------------------------------------------
__global__ void mask_kernel(const float* __restrict__ x,
                            const float* __restrict__ mw,
                            const float* __restrict__ mb,
                            float* __restrict__ masks)
{
    __shared__ float s_mw[3 * 64 * 9];
    for (int i = threadIdx.x; i < 3 * 64 * 9; i += 256) s_mw[i] = mw[i];
    __syncthreads();

    int gid = blockIdx.x * 256 + threadIdx.x;   // < 65536
    int b   = gid >> 14;
    int pid = gid & (HW - 1);
    int h   = pid >> 7;
    int w   = pid & 127;

    float a0 = mb[0], a1 = mb[1], a2 = mb[2];
    const float* xb = x + b * NC * HW;
    for (int c = 0; c < NC; c++) {
        const float* xc = xb + c * HW;
        const float* wc = s_mw + c * 9;
        #pragma unroll
        for (int kh = 0; kh < 3; kh++) {
            int hh = h + kh - 1;
            if ((unsigned)hh >= 128u) continue;
            #pragma unroll
            for (int kw = 0; kw < 3; kw++) {
                int ww = w + kw - 1;
                if ((unsigned)ww >= 128u) continue;
                float v = xc[hh * 128 + ww];
                int t = kh * 3 + kw;
                a0 = fmaf(v, wc[t],            a0);
                a1 = fmaf(v, wc[64 * 9 + t],   a1);
                a2 = fmaf(v, wc[128 * 9 + t],  a2);
            }
        }
    }
    float mx = fmaxf(a0, fmaxf(a1, a2));
    float e0 = expf(a0 - mx), e1 = expf(a1 - mx), e2 = expf(a2 - mx);
    float inv = 1.f / (e0 + e1 + e2);
    masks[(b * 3 + 0) * HW + pid] = e0 * inv;
    masks[(b * 3 + 1) * HW + pid] = e1 * inv;
    masks[(b * 3 + 2) * HW + pid] = e2 * inv;
}

// ---------------------------------------------------------------------------
// Stage 2: xm[b][m*64+c][p] = x[b][c][p] * masks[b][m][p]
// ---------------------------------------------------------------------------
__global__ void xm_kernel(const float* __restrict__ x,
                          const float* __restrict__ masks)
{
    int i = blockIdx.x * 256 + threadIdx.x;     // < 4*192*16384
    int pid = i & (HW - 1);
    int r   = i >> 14;          // b*192 + mc
    int b   = r / NMC;
    int mc  = r - b * NMC;
    int m   = mc >> 6;
    int c   = mc & 63;
    g_xm[i] = x[(b * NC + c) * HW + pid] * masks[(b * 3 + m) * HW + pid];
}

// ---------------------------------------------------------------------------
// Core conv tile: block computes 64 out-ch x (2 rows x 128 cols).
// f32x2 accumulators pack the TWO OUTPUT ROWS (h0, h0+1).
// Double-buffered smem; B filled via 4B cp.async (zfill OOB), weights
// prefetched to regs and stored duplicated. One barrier per channel-pair.
// Weight smem reads use LDS.128 (2 dup-pairs per load) to halve crossbar
// phases; weight loads are warp-uniform broadcasts.
// ---------------------------------------------------------------------------
#define BS_STRIDE (2 * 3 * 144)     // one buffer of B (float2 units)
#define WS_STRIDE (2 * 576)         // one buffer of W (float2 units)
#define NWPF 5                      // weight prefetch slots: ceil(1152/256)

template <int NIC>
__device__ __forceinline__ void conv_tile2(const float* __restrict__ xin,   // [NIC][HW]
                                           const float* __restrict__ wsrc,  // [NIC][9][64]
                                           int d, int h0,
                                           ull acc[8][4])
{
    __shared__ float2 Bs[2 * BS_STRIDE];   // [buf][ch][kh][col] row-pairs
    __shared__ __align__(16) float2 Ws[2 * WS_STRIDE];  // dup weights

    const int tid = threadIdx.x;
    const int tp = tid & 31, to = tid >> 5;
    const int Win = 128 + 2 * d;

    // This thread's B-fill slots (<=2) and smem byte addresses
    unsigned bs_base = (unsigned)__cvta_generic_to_shared(Bs);
    int lcnt = 0;
    int loff0[2], loff1[2];
    unsigned sadr[2];
    for (int idx = tid; idx < 3 * Win; idx += 256) {
        int r  = idx / Win;
        int cc = idx - r * Win;
        int win  = cc - d;
        int hin0 = h0 + (r - 1) * d;
        int hin1 = hin0 + 1;
        bool cok = (unsigned)win < 128u;
        loff0[lcnt] = (cok && (unsigned)hin0 < 128u) ? (hin0 * 128 + win) : -1;
        loff1[lcnt] = (cok && (unsigned)hin1 < 128u) ? (hin1 * 128 + win) : -1;
        sadr[lcnt]  = bs_base + (unsigned)(r * 144 + cc) * 8u;
        lcnt++;
    }

    #pragma unroll
    for (int i = 0; i < 8; i++)
        #pragma unroll
        for (int j = 0; j < 4; j++) acc[i][j] = 0ull;

    float wreg[NWPF];

    // ---- prologue: fill buffer 0 with pair 0 ----
    {
        #pragma unroll
        for (int s = 0; s < 2; s++) {
            const float* xc = xin + s * HW;
            unsigned so = (unsigned)(s * 3 * 144) * 8u;
            for (int l = 0; l < lcnt; l++) {
                const float* p0 = (loff0[l] >= 0) ? xc + loff0[l] : xc;
                const float* p1 = (loff1[l] >= 0) ? xc + loff1[l] : xc;
                CP4(sadr[l] + so,      p0, (loff0[l] >= 0) ? 4 : 0);
                CP4(sadr[l] + so + 4,  p1, (loff1[l] >= 0) ? 4 : 0);
            }
        }
        CP_COMMIT();
        #pragma unroll
        for (int l = 0; l < NWPF; l++) {
            int f = tid + 256 * l;
            if (f < 1152) wreg[l] = __ldg(wsrc + f);
        }
        CP_WAIT0();
        #pragma unroll
        for (int l = 0; l < NWPF; l++) {
            int f = tid + 256 * l;
            if (f < 1152) Ws[f] = make_float2(wreg[l], wreg[l]);
        }
    }
    __syncthreads();

    const int NPAIR = NIC / 2;
    for (int k = 0; k < NPAIR; k++) {
        const int cur = k & 1, nxt = cur ^ 1;
        const int mc2 = 2 * (k + 1);
        const bool more = (k + 1) < NPAIR;

        // issue next pair's B fills + weight LDGs (overlap with math)
        if (more) {
            unsigned bufo = (unsigned)(nxt * BS_STRIDE) * 8u;
            #pragma unroll
            for (int s = 0; s < 2; s++) {
                const float* xc = xin + (mc2 + s) * HW;
                unsigned so = bufo + (unsigned)(s * 3 * 144) * 8u;
                for (int l = 0; l < lcnt; l++) {
                    const float* p0 = (loff0[l] >= 0) ? xc + loff0[l] : xc;
                    const float* p1 = (loff1[l] >= 0) ? xc + loff1[l] : xc;
                    CP4(sadr[l] + so,     p0, (loff0[l] >= 0) ? 4 : 0);
                    CP4(sadr[l] + so + 4, p1, (loff1[l] >= 0) ? 4 : 0);
                }
            }
            const float* wp = wsrc + mc2 * 576;
            #pragma unroll
            for (int l = 0; l < NWPF; l++) {
                int f = tid + 256 * l;
                if (f < 1152) wreg[l] = __ldg(wp + f);
            }
        }
        CP_COMMIT();

        // ---- math on current buffer ----
        const float2* bsb = Bs + cur * BS_STRIDE;
        const float2* wsb = Ws + cur * WS_STRIDE;
        #pragma unroll
        for (int s = 0; s < 2; s++) {
            const float2* ws = wsb + s * 576;
            const float2* bs = bsb + s * 3 * 144;
            #pragma unroll
            for (int t = 0; t < 9; t++) {
                const int kh = t / 3, kw = t - kh * 3;
                const ulonglong2* wp =
                    (const ulonglong2*)(ws + t * 64 + to * 8);
                ulonglong2 wq0 = wp[0], wq1 = wp[1], wq2 = wp[2], wq3 = wp[3];
                const ull* bp = (const ull*)(bs + kh * 144 + tp + kw * d);
                ull b0 = bp[0], b1 = bp[32], b2 = bp[64], b3 = bp[96];
                #pragma unroll
                for (int j = 0; j < 4; j++) {
                    ull bv = (j == 0) ? b0 : (j == 1) ? b1 : (j == 2) ? b2 : b3;
                    FMA2(acc[0][j], wq0.x, bv);
                    FMA2(acc[1][j], wq0.y, bv);
                    FMA2(acc[2][j], wq1.x, bv);
                    FMA2(acc[3][j], wq1.y, bv);
                    FMA2(acc[4][j], wq2.x, bv);
                    FMA2(acc[5][j], wq2.y, bv);
                    FMA2(acc[6][j], wq3.x, bv);
                    FMA2(acc[7][j], wq3.y, bv);
                }
            }
        }

        CP_WAIT0();
        if (more) {
            float2* wd = Ws + nxt * WS_STRIDE;
            #pragma unroll
            for (int l = 0; l < NWPF; l++) {
                int f = tid + 256 * l;
                if (f < 1152) wd[f] = make_float2(wreg[l], wreg[l]);
            }
        }
        __syncthreads();
    }
}

// ---------------------------------------------------------------------------
// Stage 3: per (b, dilation) dense conv Cin=192 -> Cout=64, write into g_cat
// ---------------------------------------------------------------------------
__global__ void __launch_bounds__(256, 2) branch_kernel()
{
    int blk = blockIdx.x;              // [0, 1024)
    int hp = blk & 63;
    int di = (blk >> 6) & 3;
    int b  = blk >> 8;
    int d  = 2 * di + 1;               // 1,3,5,7
    int h0 = hp * 2;

    ull acc[8][4];
    conv_tile2<NMC>(g_xm + b * NMC * HW, g_wbr + b * NMC * 576, d, h0, acc);

    int tp = threadIdx.x & 31, to = threadIdx.x >> 5;
    float* cb = g_cat + (b * NIC2 + di * 64) * HW;
    #pragma unroll
    for (int i = 0; i < 8; i++) {
        float* cbo = cb + (to * 8 + i) * HW + h0 * 128;
        #pragma unroll
        for (int j = 0; j < 4; j++) {
            float2 v = *(float2*)&acc[i][j];
            int w_ = tp + 32 * j;
            cbo[w_]       = v.x;
            cbo[128 + w_] = v.y;
        }
    }
}

// ---------------------------------------------------------------------------
// Stage 4: fuse conv Cin=256 -> Cout=64 (dil 1) + bias + BN(eval) + ReLU
// ---------------------------------------------------------------------------
__global__ void __launch_bounds__(256, 2) out_kernel(const float* __restrict__ cob,
                                                     const float* __restrict__ gamma,
                                                     const float* __restrict__ beta,
                                                     const float* __restrict__ mean,
                                                     const float* __restrict__ var,
                                                     float* __restrict__ out)
{
    int blk = blockIdx.x;              // [0, 256)
    int hp = blk & 63;
    int b  = blk >> 6;
    int h0 = hp * 2;

    ull acc[8][4];
    conv_tile2<NIC2>(g_cat + b * NIC2 * HW, g_wout, 1, h0, acc);

    int tp = threadIdx.x & 31, to = threadIdx.x >> 5;
    #pragma unroll
    for (int i = 0; i < 8; i++) {
        int o = to * 8 + i;
        float inv  = gamma[o] * rsqrtf(var[o] + 1e-5f);
        float addv = beta[o] - mean[o] * inv;
        float bias = cob[o];
        float* po = out + (b * NO + o) * HW + h0 * 128;
        #pragma unroll
        for (int j = 0; j < 4; j++) {
            float2 v = *(float2*)&acc[i][j];
            int w_ = tp + 32 * j;
            po[w_]       = fmaxf((v.x + bias) * inv + addv, 0.f);
            po[128 + w_] = fmaxf((v.y + bias) * inv + addv, 0.f);
        }
    }
}

// ---------------------------------------------------------------------------
extern "C" void kernel_launch(void* const* d_in, const int* in_sizes, int n_in,
                              void* d_out, int out_size)
{
    const float* x     = (const float*)d_in[0];
    const float* kern  = (const float*)d_in[1];
    const float* mw    = (const float*)d_in[2];
    const float* mb    = (const float*)d_in[3];
    const float* cow   = (const float*)d_in[4];
    const float* cob   = (const float*)d_in[5];
    const float* gamma = (const float*)d_in[6];
    const float* beta  = (const float*)d_in[7];
    const float* mean  = (const float*)d_in[8];
    const float* var   = (const float*)d_in[9];

    float* out   = (float*)d_out;
    float* masks = out + NB * NO * HW;   // tuple output: (out, masks)

    prep_w_kernel<<<1728, 256>>>(kern, cow);
    mask_kernel<<<NB * HW / 256, 256>>>(x, mw, mb, masks);
    xm_kernel<<<NB * NMC * HW / 256, 256>>>(x, masks);
    branch_kernel<<<NB * 4 * 64, 256>>>();
    out_kernel<<<NB * 64, 256>>>(cob, gamma, beta, mean, var, out);
}

// round 6
// speedup vs baseline: 1.0028x; 1.0028x over previous
#include <cuda_runtime.h>
#include <math.h>

// Problem constants
#define HH 128
#define WW 128
#define HW 16384        // 128*128
#define NB 4            // batch
#define NC 64           // in channels
#define NO 64           // out channels
#define NMC 192         // 3 masks * 64 channels
#define NIC2 256        // 4 dilations * 64

typedef unsigned long long ull;

// Scratch (device globals: allocation-free per harness rules)
__device__ float g_xm[NB * NMC * HW];        // 50.3 MB: x * mask, fused (m,c) channels
__device__ float g_cat[NB * NIC2 * HW];      // 67.1 MB: concatenated branch outputs
__device__ float g_wbr[NB * NMC * 9 * 64];   // packed branch weights [b][mc][tap][o]
__device__ float g_wout[NIC2 * 9 * 64];      // packed fuse weights  [ic][tap][o]

// Packed dual-fp32 FMA (sm_103a FFMA2; ptxas never auto-fuses this)
#define FMA2(acc, a, b) \
    asm("fma.rn.f32x2 %0, %1, %2, %0;" : "+l"(acc) : "l"(a), "l"(b))

// 4-byte cp.async with zero-fill when sz==0 (OOB padding)
#define CP4(saddr, gptr, sz) \
    asm volatile("cp.async.ca.shared.global [%0], [%1], 4, %2;" \
                 :: "r"(saddr), "l"(gptr), "r"(sz))
#define CP_COMMIT() asm volatile("cp.async.commit_group;")
#define CP_WAIT0()  asm volatile("cp.async.wait_group 0;")

// ---------------------------------------------------------------------------
// Weight prepack: branch weights kernel[b,m,o,c,kh,kw] -> [b][mc=m*64+c][tap][o]
//                 fuse weights conv_out_w[o,ic,kh,kw]  -> [ic][tap][o]
// ---------------------------------------------------------------------------
__global__ void prep_w_kernel(const float* __restrict__ kern,
                              const float* __restrict__ cow)
{
    int i = blockIdx.x * 256 + threadIdx.x;
    if (i < NB * NMC * 9 * 64) {
        int o   = i & 63;
        int rt  = i >> 6;        // r*9 + tap
        int tap = rt % 9;
        int r   = rt / 9;        // b*192 + mc
        int b   = r / NMC;
        int mc  = r - b * NMC;
        int m   = mc >> 6;
        int c   = mc & 63;
        g_wbr[i] = kern[(((b * 3 + m) * 64 + o) * 64 + c) * 9 + tap];
    }
    if (i < NIC2 * 9 * 64) {
        int o   = i & 63;
        int rt  = i >> 6;
        int tap = rt % 9;
        int ic  = rt / 9;
        g_wout[i] = cow[(o * NIC2 + ic) * 9 + tap];
    }
}

// ---------------------------------------------------------------------------
// Stage 1: mask conv (3x3, pad 1) + channel softmax over 3. One thread/pixel.
// ---------------------------------------------------------------------------
__global__ void mask_kernel(const float* __restrict__ x,
                            const float* __restrict__ mw,
                            const float* __restrict__ mb,
                            float* __restrict__ masks)
{
    __shared__ float s_mw[3 * 64 * 9];
    for (int i = threadIdx.x; i < 3 * 64 * 9; i += 256) s_mw[i] = mw[i];
    __syncthreads();

    int gid = blockIdx.x * 256 + threadIdx.x;   // < 65536
    int b   = gid >> 14;
    int pid = gid & (HW - 1);
    int h   = pid >> 7;
    int w   = pid & 127;

    float a0 = mb[0], a1 = mb[1], a2 = mb[2];
    const float* xb = x + b * NC * HW;
    for (int c = 0; c < NC; c++) {
        const float* xc = xb + c * HW;
        const float* wc = s_mw + c * 9;
        #pragma unroll
        for (int kh = 0; kh < 3; kh++) {
            int hh = h + kh - 1;
            if ((unsigned)hh >= 128u) continue;
            #pragma unroll
            for (int kw = 0; kw < 3; kw++) {
                int ww = w + kw - 1;
                if ((unsigned)ww >= 128u) continue;
                float v = xc[hh * 128 + ww];
                int t = kh * 3 + kw;
                a0 = fmaf(v, wc[t],            a0);
                a1 = fmaf(v, wc[64 * 9 + t],   a1);
                a2 = fmaf(v, wc[128 * 9 + t],  a2);
            }
        }
    }
    float mx = fmaxf(a0, fmaxf(a1, a2));
    float e0 = expf(a0 - mx), e1 = expf(a1 - mx), e2 = expf(a2 - mx);
    float inv = 1.f / (e0 + e1 + e2);
    masks[(b * 3 + 0) * HW + pid] = e0 * inv;
    masks[(b * 3 + 1) * HW + pid] = e1 * inv;
    masks[(b * 3 + 2) * HW + pid] = e2 * inv;
}

// ---------------------------------------------------------------------------
// Stage 2: xm[b][m*64+c][p] = x[b][c][p] * masks[b][m][p]
// ---------------------------------------------------------------------------
__global__ void xm_kernel(const float* __restrict__ x,
                          const float* __restrict__ masks)
{
    int i = blockIdx.x * 256 + threadIdx.x;     // < 4*192*16384
    int pid = i & (HW - 1);
    int r   = i >> 14;          // b*192 + mc
    int b   = r / NMC;
    int mc  = r - b * NMC;
    int m   = mc >> 6;
    int c   = mc & 63;
    g_xm[i] = x[(b * NC + c) * HW + pid] * masks[(b * 3 + m) * HW + pid];
}

// ---------------------------------------------------------------------------
// Core conv tile: block computes 64 out-ch x (2 rows x 128 cols).
// f32x2 accumulators pack the TWO OUTPUT ROWS (h0, h0+1).
// Double-buffered smem; B filled via 4B cp.async (zfill OOB), weights
// prefetched to regs and stored duplicated. One barrier per channel-pair.
// Weight smem reads use LDS.128 (2 dup-pairs per load) to halve crossbar
// phases; weight loads are warp-uniform broadcasts.
// ---------------------------------------------------------------------------
#define BS_STRIDE (2 * 3 * 144)     // one buffer of B (float2 units)
#define WS_STRIDE (2 * 576)         // one buffer of W (float2 units)
#define NWPF 5                      // weight prefetch slots: ceil(1152/256)

template <int NIC>
__device__ __forceinline__ void conv_tile2(const float* __restrict__ xin,   // [NIC][HW]
                                           const float* __restrict__ wsrc,  // [NIC][9][64]
                                           int d, int h0,
                                           ull acc[8][4])
{
    __shared__ float2 Bs[2 * BS_STRIDE];   // [buf][ch][kh][col] row-pairs
    __shared__ __align__(16) float2 Ws[2 * WS_STRIDE];  // dup weights

    const int tid = threadIdx.x;
    const int tp = tid & 31, to = tid >> 5;
    const int Win = 128 + 2 * d;

    // This thread's B-fill slots (<=2) and smem byte addresses
    unsigned bs_base = (unsigned)__cvta_generic_to_shared(Bs);
    int lcnt = 0;
    int loff0[2], loff1[2];
    unsigned sadr[2];
    for (int idx = tid; idx < 3 * Win; idx += 256) {
        int r  = idx / Win;
        int cc = idx - r * Win;
        int win  = cc - d;
        int hin0 = h0 + (r - 1) * d;
        int hin1 = hin0 + 1;
        bool cok = (unsigned)win < 128u;
        loff0[lcnt] = (cok && (unsigned)hin0 < 128u) ? (hin0 * 128 + win) : -1;
        loff1[lcnt] = (cok && (unsigned)hin1 < 128u) ? (hin1 * 128 + win) : -1;
        sadr[lcnt]  = bs_base + (unsigned)(r * 144 + cc) * 8u;
        lcnt++;
    }

    #pragma unroll
    for (int i = 0; i < 8; i++)
        #pragma unroll
        for (int j = 0; j < 4; j++) acc[i][j] = 0ull;

    float wreg[NWPF];

    // ---- prologue: fill buffer 0 with pair 0 ----
    {
        #pragma unroll
        for (int s = 0; s < 2; s++) {
            const float* xc = xin + s * HW;
            unsigned so = (unsigned)(s * 3 * 144) * 8u;
            for (int l = 0; l < lcnt; l++) {
                const float* p0 = (loff0[l] >= 0) ? xc + loff0[l] : xc;
                const float* p1 = (loff1[l] >= 0) ? xc + loff1[l] : xc;
                CP4(sadr[l] + so,      p0, (loff0[l] >= 0) ? 4 : 0);
                CP4(sadr[l] + so + 4,  p1, (loff1[l] >= 0) ? 4 : 0);
            }
        }
        CP_COMMIT();
        #pragma unroll
        for (int l = 0; l < NWPF; l++) {
            int f = tid + 256 * l;
            if (f < 1152) wreg[l] = __ldg(wsrc + f);
        }
        CP_WAIT0();
        #pragma unroll
        for (int l = 0; l < NWPF; l++) {
            int f = tid + 256 * l;
            if (f < 1152) Ws[f] = make_float2(wreg[l], wreg[l]);
        }
    }
    __syncthreads();

    const int NPAIR = NIC / 2;
    for (int k = 0; k < NPAIR; k++) {
        const int cur = k & 1, nxt = cur ^ 1;
        const int mc2 = 2 * (k + 1);
        const bool more = (k + 1) < NPAIR;

        // issue next pair's B fills + weight LDGs (overlap with math)
        if (more) {
            unsigned bufo = (unsigned)(nxt * BS_STRIDE) * 8u;
            #pragma unroll
            for (int s = 0; s < 2; s++) {
                const float* xc = xin + (mc2 + s) * HW;
                unsigned so = bufo + (unsigned)(s * 3 * 144) * 8u;
                for (int l = 0; l < lcnt; l++) {
                    const float* p0 = (loff0[l] >= 0) ? xc + loff0[l] : xc;
                    const float* p1 = (loff1[l] >= 0) ? xc + loff1[l] : xc;
                    CP4(sadr[l] + so,     p0, (loff0[l] >= 0) ? 4 : 0);
                    CP4(sadr[l] + so + 4, p1, (loff1[l] >= 0) ? 4 : 0);
                }
            }
            const float* wp = wsrc + mc2 * 576;
            #pragma unroll
            for (int l = 0; l < NWPF; l++) {
                int f = tid + 256 * l;
                if (f < 1152) wreg[l] = __ldg(wp + f);
            }
        }
        CP_COMMIT();

        // ---- math on current buffer ----
        const float2* bsb = Bs + cur * BS_STRIDE;
        const float2* wsb = Ws + cur * WS_STRIDE;
        #pragma unroll
        for (int s = 0; s < 2; s++) {
            const float2* ws = wsb + s * 576;
            const float2* bs = bsb + s * 3 * 144;
            #pragma unroll
            for (int t = 0; t < 9; t++) {
                const int kh = t / 3, kw = t - kh * 3;
                const ulonglong2* wp =
                    (const ulonglong2*)(ws + t * 64 + to * 8);
                ulonglong2 wq0 = wp[0], wq1 = wp[1], wq2 = wp[2], wq3 = wp[3];
                const ull* bp = (const ull*)(bs + kh * 144 + tp + kw * d);
                ull b0 = bp[0], b1 = bp[32], b2 = bp[64], b3 = bp[96];
                #pragma unroll
                for (int j = 0; j < 4; j++) {
                    ull bv = (j == 0) ? b0 : (j == 1) ? b1 : (j == 2) ? b2 : b3;
                    FMA2(acc[0][j], wq0.x, bv);
                    FMA2(acc[1][j], wq0.y, bv);
                    FMA2(acc[2][j], wq1.x, bv);
                    FMA2(acc[3][j], wq1.y, bv);
                    FMA2(acc[4][j], wq2.x, bv);
                    FMA2(acc[5][j], wq2.y, bv);
                    FMA2(acc[6][j], wq3.x, bv);
                    FMA2(acc[7][j], wq3.y, bv);
                }
            }
        }

        CP_WAIT0();
        if (more) {
            float2* wd = Ws + nxt * WS_STRIDE;
            #pragma unroll
            for (int l = 0; l < NWPF; l++) {
                int f = tid + 256 * l;
                if (f < 1152) wd[f] = make_float2(wreg[l], wreg[l]);
            }
        }
        __syncthreads();
    }
}

// ---------------------------------------------------------------------------
// Stage 3: per (b, dilation) dense conv Cin=192 -> Cout=64, write into g_cat
// ---------------------------------------------------------------------------
__global__ void __launch_bounds__(256, 2) branch_kernel()
{
    int blk = blockIdx.x;              // [0, 1024)
    int hp = blk & 63;
    int di = (blk >> 6) & 3;
    int b  = blk >> 8;
    int d  = 2 * di + 1;               // 1,3,5,7
    int h0 = hp * 2;

    ull acc[8][4];
    conv_tile2<NMC>(g_xm + b * NMC * HW, g_wbr + b * NMC * 576, d, h0, acc);

    int tp = threadIdx.x & 31, to = threadIdx.x >> 5;
    float* cb = g_cat + (b * NIC2 + di * 64) * HW;
    #pragma unroll
    for (int i = 0; i < 8; i++) {
        float* cbo = cb + (to * 8 + i) * HW + h0 * 128;
        #pragma unroll
        for (int j = 0; j < 4; j++) {
            float2 v = *(float2*)&acc[i][j];
            int w_ = tp + 32 * j;
            cbo[w_]       = v.x;
            cbo[128 + w_] = v.y;
        }
    }
}

// ---------------------------------------------------------------------------
// Stage 4: fuse conv Cin=256 -> Cout=64 (dil 1) + bias + BN(eval) + ReLU
// ---------------------------------------------------------------------------
__global__ void __launch_bounds__(256, 2) out_kernel(const float* __restrict__ cob,
                                                     const float* __restrict__ gamma,
                                                     const float* __restrict__ beta,
                                                     const float* __restrict__ mean,
                                                     const float* __restrict__ var,
                                                     float* __restrict__ out)
{
    int blk = blockIdx.x;              // [0, 256)
    int hp = blk & 63;
    int b  = blk >> 6;
    int h0 = hp * 2;

    ull acc[8][4];
    conv_tile2<NIC2>(g_cat + b * NIC2 * HW, g_wout, 1, h0, acc);

    int tp = threadIdx.x & 31, to = threadIdx.x >> 5;
    #pragma unroll
    for (int i = 0; i < 8; i++) {
        int o = to * 8 + i;
        float inv  = gamma[o] * rsqrtf(var[o] + 1e-5f);
        float addv = beta[o] - mean[o] * inv;
        float bias = cob[o];
        float* po = out + (b * NO + o) * HW + h0 * 128;
        #pragma unroll
        for (int j = 0; j < 4; j++) {
            float2 v = *(float2*)&acc[i][j];
            int w_ = tp + 32 * j;
            po[w_]       = fmaxf((v.x + bias) * inv + addv, 0.f);
            po[128 + w_] = fmaxf((v.y + bias) * inv + addv, 0.f);
        }
    }
}

// ---------------------------------------------------------------------------
extern "C" void kernel_launch(void* const* d_in, const int* in_sizes, int n_in,
                              void* d_out, int out_size)
{
    const float* x     = (const float*)d_in[0];
    const float* kern  = (const float*)d_in[1];
    const float* mw    = (const float*)d_in[2];
    const float* mb    = (const float*)d_in[3];
    const float* cow   = (const float*)d_in[4];
    const float* cob   = (const float*)d_in[5];
    const float* gamma = (const float*)d_in[6];
    const float* beta  = (const float*)d_in[7];
    const float* mean  = (const float*)d_in[8];
    const float* var   = (const float*)d_in[9];

    float* out   = (float*)d_out;
    float* masks = out + NB * NO * HW;   // tuple output: (out, masks)

    prep_w_kernel<<<1728, 256>>>(kern, cow);
    mask_kernel<<<NB * HW / 256, 256>>>(x, mw, mb, masks);
    xm_kernel<<<NB * NMC * HW / 256, 256>>>(x, masks);
    branch_kernel<<<NB * 4 * 64, 256>>>();
    out_kernel<<<NB * 64, 256>>>(cob, gamma, beta, mean, var, out);
}

// round 8
// speedup vs baseline: 2.4907x; 2.4838x over previous
#include <cuda_runtime.h>
#include <cuda_bf16.h>
#include <stdint.h>
#include <math.h>

#define HW 16384
#define RLEN 9088         // padded row: 448 + 128*64 + 448 elems
#define NROWS 144         // h = -8 .. 135
typedef unsigned u32; typedef unsigned long long u64;

// ---------------- device scratch (zero-initialized; pads never written) ----
__device__ __align__(256) __nv_bfloat16 g_xA_h[12 * NROWS * RLEN];
__device__ __align__(256) __nv_bfloat16 g_xA_l[12 * NROWS * RLEN];
__device__ __align__(256) __nv_bfloat16 g_cA_h[16 * NROWS * RLEN];
__device__ __align__(256) __nv_bfloat16 g_cA_l[16 * NROWS * RLEN];
__device__ __align__(256) __nv_bfloat16 g_wb_h[4 * 27 * 4096];
__device__ __align__(256) __nv_bfloat16 g_wb_l[4 * 27 * 4096];
__device__ __align__(256) __nv_bfloat16 g_wo_h[36 * 4096];
__device__ __align__(256) __nv_bfloat16 g_wo_l[36 * 4096];

// ---------------- PTX helpers ----------------------------------------------
__device__ __forceinline__ u32 s2u(const void* p){
    u32 a; asm("{ .reg .u64 t; cvta.to.shared.u64 t, %1; cvt.u32.u64 %0, t; }"
               : "=r"(a) : "l"(p)); return a;
}
#define CP16(dst, src) \
    asm volatile("cp.async.cg.shared.global [%0], [%1], 16;" :: "r"(dst), "l"(src) : "memory")
#define CP_COMMIT() asm volatile("cp.async.commit_group;" ::: "memory")
#define CP_WAIT1()  asm volatile("cp.async.wait_group 1;" ::: "memory")
#define LDX4(r, a) \
    asm volatile("ldmatrix.sync.aligned.m8n8.x4.shared.b16 {%0,%1,%2,%3}, [%4];" \
        : "=r"((r)[0]), "=r"((r)[1]), "=r"((r)[2]), "=r"((r)[3]) : "r"(a))
#define MMA(d, a, b0, b1) \
    asm("mma.sync.aligned.m16n8k16.row.col.f32.bf16.bf16.f32 " \
        "{%0,%1,%2,%3},{%4,%5,%6,%7},{%8,%9},{%0,%1,%2,%3};" \
        : "+f"((d)[0]), "+f"((d)[1]), "+f"((d)[2]), "+f"((d)[3]) \
        : "r"((a)[0]), "r"((a)[1]), "r"((a)[2]), "r"((a)[3]), "r"(b0), "r"(b1))

__device__ __forceinline__ void split2(float v0, float v1, u32& hw, u32& lw){
    __nv_bfloat16 h0 = __float2bfloat16(v0);
    __nv_bfloat16 h1 = __float2bfloat16(v1);
    __nv_bfloat16 l0 = __float2bfloat16(v0 - __bfloat162float(h0));
    __nv_bfloat16 l1 = __float2bfloat16(v1 - __bfloat162float(h1));
    hw = (u32)*(unsigned short*)&h0 | ((u32)*(unsigned short*)&h1 << 16);
    lw = (u32)*(unsigned short*)&l0 | ((u32)*(unsigned short*)&l1 << 16);
}

// ---------------- stage 1: mask conv + softmax ------------------------------
__global__ void mask_kernel(const float* __restrict__ x, const float* __restrict__ mw,
                            const float* __restrict__ mb, float* __restrict__ masks)
{
    __shared__ float s_mw[3*64*9];
    for (int i = threadIdx.x; i < 3*64*9; i += 256) s_mw[i] = mw[i];
    __syncthreads();
    int gid = blockIdx.x*256 + threadIdx.x;
    int b = gid >> 14, pid = gid & (HW-1), h = pid >> 7, w = pid & 127;
    float a0 = mb[0], a1 = mb[1], a2 = mb[2];
    const float* xb = x + b*64*HW;
    for (int c = 0; c < 64; c++){
        const float* xc = xb + c*HW; const float* wc = s_mw + c*9;
        #pragma unroll
        for (int kh = 0; kh < 3; kh++){
            int hh = h + kh - 1; if ((unsigned)hh >= 128u) continue;
            #pragma unroll
            for (int kw = 0; kw < 3; kw++){
                int ww = w + kw - 1; if ((unsigned)ww >= 128u) continue;
                float v = xc[hh*128 + ww]; int t = kh*3 + kw;
                a0 = fmaf(v, wc[t], a0); a1 = fmaf(v, wc[576+t], a1); a2 = fmaf(v, wc[1152+t], a2);
            }
        }
    }
    float mx = fmaxf(a0, fmaxf(a1, a2));
    float e0 = expf(a0-mx), e1 = expf(a1-mx), e2 = expf(a2-mx);
    float inv = 1.f/(e0+e1+e2);
    masks[(b*3+0)*HW+pid] = e0*inv; masks[(b*3+1)*HW+pid] = e1*inv; masks[(b*3+2)*HW+pid] = e2*inv;
}

// ---------------- stage 2: transpose + split xm into padded layout ----------
__global__ void xmT_kernel(const float* __restrict__ x, const float* __restrict__ masks)
{
    __shared__ float sx[64*129];
    __shared__ float sm[128];
    int bx = blockIdx.x;                 // (bm<<7)|h
    int h = bx & 127, bm = bx >> 7, m = bm % 3, b = bm / 3;
    for (int idx = threadIdx.x; idx < 8192; idx += 256){
        int c = idx >> 7, w = idx & 127;
        sx[c*129 + w] = x[(b*64 + c)*HW + h*128 + w];
    }
    if (threadIdx.x < 128) sm[threadIdx.x] = masks[bm*HW + h*128 + threadIdx.x];
    __syncthreads();
    size_t base = ((size_t)bm*NROWS + (h+8))*RLEN + 448;
    for (int idx = threadIdx.x; idx < 4096; idx += 256){
        int w = idx >> 5, c2 = (idx & 31)*2;
        float v0 = sx[c2*129 + w] * sm[w];
        float v1 = sx[(c2+1)*129 + w] * sm[w];
        u32 hw, lw; split2(v0, v1, hw, lw);
        size_t e = base + (size_t)w*64 + c2;
        *(u32*)(g_xA_h + e) = hw;
        *(u32*)(g_xA_l + e) = lw;
    }
}

// ---------------- weight prep: split B tiles [tile][o][c] -------------------
__global__ void wprep_kernel(const float* __restrict__ kern, const float* __restrict__ cow)
{
    int i = blockIdx.x*256 + threadIdx.x;
    if (i < 4*27*4096){
        int tile = i >> 12, e = i & 4095, o = e >> 6, c = e & 63;
        int b = tile / 27, r = tile % 27, tap = r / 3, m = r % 3;
        float v = kern[(((b*3 + m)*64 + o)*64 + c)*9 + tap];
        __nv_bfloat16 hi = __float2bfloat16(v);
        g_wb_h[i] = hi;
        g_wb_l[i] = __float2bfloat16(v - __bfloat162float(hi));
    }
    if (i < 36*4096){
        int tile = i >> 12, e = i & 4095, o = e >> 6, c = e & 63;
        int tap = tile / 4, ch = tile % 4;
        float v = cow[(o*256 + ch*64 + c)*9 + tap];
        __nv_bfloat16 hi = __float2bfloat16(v);
        g_wo_h[i] = hi;
        g_wo_l[i] = __float2bfloat16(v - __bfloat162float(hi));
    }
}

// ---------------- MMA mainloop ----------------------------------------------
// smem (bytes): A: [buf][hi,lo] 128x72 bf16 = 18432 each -> buf stride 36864
//               B: at 73728 + [buf][hi,lo] 64x72 bf16 = 9216 each -> buf stride 18432
// total 110592 bytes.
template<int NS, int NCH>
__device__ __forceinline__ void mma_mainloop(
    const __nv_bfloat16* __restrict__ xah, const __nv_bfloat16* __restrict__ xal,
    const __nv_bfloat16* __restrict__ wth, const __nv_bfloat16* __restrict__ wtl,
    int d, int h, float acc[8][4])
{
    extern __shared__ __align__(16) unsigned char smraw[];
    u32 sm0 = s2u(smraw);
    const int tid = threadIdx.x, lane = tid & 31, wid = tid >> 5;

    #pragma unroll
    for (int i = 0; i < 8; i++)
        #pragma unroll
        for (int j = 0; j < 4; j++) acc[i][j] = 0.f;

    auto issue = [&](int s, int buf){
        int tap = s / NCH, ch = s - tap*NCH;
        int dh = (tap/3 - 1)*d, dw = (tap%3 - 1)*d;
        size_t arow = ((size_t)ch*NROWS + (h + 8 + dh))*RLEN + 448 + (long)dw*64;
        u32 abase = sm0 + (u32)buf*36864u;
        #pragma unroll
        for (int t = 0; t < 4; t++){
            int idx = tid + t*256; int w = idx >> 3, c16 = idx & 7;
            size_t off = arow + (size_t)w*64 + c16*8;
            u32 dst = abase + (u32)(w*144 + c16*16);
            CP16(dst,          xah + off);
            CP16(dst + 18432u, xal + off);
        }
        u32 bbase = sm0 + 73728u + (u32)buf*18432u;
        const __nv_bfloat16* wsh = wth + (size_t)s*4096;
        const __nv_bfloat16* wsl = wtl + (size_t)s*4096;
        #pragma unroll
        for (int t = 0; t < 2; t++){
            int idx = tid + t*256; int o = idx >> 3, c16 = idx & 7;
            u32 dst = bbase + (u32)(o*144 + c16*16);
            CP16(dst,         wsh + o*64 + c16*8);
            CP16(dst + 9216u, wsl + o*64 + c16*8);
        }
    };

    issue(0, 0); CP_COMMIT();
    issue(1, 1); CP_COMMIT();

    const u32 a_lane = (u32)((wid*16 + (lane & 15))*144 + (lane >> 4)*16);
    const int br = lane & 7, bq = lane >> 3;
    const u32 b_lane0 = (u32)((br + (bq >> 1)*8)*144 + (bq & 1)*16);

    for (int s = 0; s < NS; s++){
        int buf = s & 1;
        CP_WAIT1();
        __syncthreads();
        u32 ab = sm0 + (u32)buf*36864u + a_lane;
        u32 bb = sm0 + 73728u + (u32)buf*18432u + b_lane0;
        #pragma unroll
        for (int ks = 0; ks < 4; ks++){
            u32 ah[4], al[4];
            LDX4(ah, ab + ks*32);
            LDX4(al, ab + ks*32 + 18432u);
            #pragma unroll
            for (int np = 0; np < 4; np++){
                u32 bh[4], bl[4];
                u32 ba = bb + (u32)(np*16*144) + ks*32;
                LDX4(bh, ba);
                LDX4(bl, ba + 9216u);
                MMA(acc[2*np],   ah, bh[0], bh[1]);
                MMA(acc[2*np],   ah, bl[0], bl[1]);
                MMA(acc[2*np],   al, bh[0], bh[1]);
                MMA(acc[2*np+1], ah, bh[2], bh[3]);
                MMA(acc[2*np+1], ah, bl[2], bl[3]);
                MMA(acc[2*np+1], al, bh[2], bh[3]);
            }
        }
        __syncthreads();
        if (s + 2 < NS) issue(s + 2, buf);
        CP_COMMIT();
    }
}

// ---------------- branch conv: writes split cat tiles ------------------------
__global__ void __launch_bounds__(256, 1)
branch_mma()
{
    int bx = blockIdx.x;                  // h | di<<7 | b<<9
    int h = bx & 127, di = (bx >> 7) & 3, b = bx >> 9;
    int d = 2*di + 1;

    float acc[8][4];
    mma_mainloop<27, 3>(g_xA_h + (size_t)(b*3)*NROWS*RLEN,
                        g_xA_l + (size_t)(b*3)*NROWS*RLEN,
                        g_wb_h + (size_t)b*27*4096,
                        g_wb_l + (size_t)b*27*4096, d, h, acc);

    const int lane = threadIdx.x & 31, wid = threadIdx.x >> 5;
    const int w0 = wid*16, g = lane >> 2, tig = lane & 3;
    size_t cb = ((size_t)(b*4 + di)*NROWS + (h + 8))*RLEN + 448;
    #pragma unroll
    for (int nt = 0; nt < 8; nt++){
        int o = nt*8 + 2*tig;
        u32 hw, lw;
        split2(acc[nt][0], acc[nt][1], hw, lw);
        size_t e0 = cb + (size_t)(w0 + g)*64 + o;
        *(u32*)(g_cA_h + e0) = hw; *(u32*)(g_cA_l + e0) = lw;
        split2(acc[nt][2], acc[nt][3], hw, lw);
        size_t e1 = cb + (size_t)(w0 + g + 8)*64 + o;
        *(u32*)(g_cA_h + e1) = hw; *(u32*)(g_cA_l + e1) = lw;
    }
}

// ---------------- out conv + bias + BN + ReLU --------------------------------
__global__ void __launch_bounds__(256, 1)
out_mma(const float* __restrict__ cob, const float* __restrict__ gamma,
        const float* __restrict__ beta, const float* __restrict__ mean,
        const float* __restrict__ var, float* __restrict__ out)
{
    __shared__ float sInv[64], sAdd[64], sBias[64];
    int bx = blockIdx.x;                  // h | b<<7
    int h = bx & 127, b = bx >> 7;
    if (threadIdx.x < 64){
        int o = threadIdx.x;
        float inv = gamma[o] * rsqrtf(var[o] + 1e-5f);
        sInv[o] = inv; sAdd[o] = beta[o] - mean[o]*inv; sBias[o] = cob[o];
    }

    float acc[8][4];
    mma_mainloop<36, 4>(g_cA_h + (size_t)(b*4)*NROWS*RLEN,
                        g_cA_l + (size_t)(b*4)*NROWS*RLEN,
                        g_wo_h, g_wo_l, 1, h, acc);

    const int lane = threadIdx.x & 31, wid = threadIdx.x >> 5;
    const int w0 = wid*16, g = lane >> 2, tig = lane & 3;
    #pragma unroll
    for (int nt = 0; nt < 8; nt++){
        int o = nt*8 + 2*tig;
        float i0 = sInv[o], a0 = sAdd[o], c0 = sBias[o];
        float i1 = sInv[o+1], a1 = sAdd[o+1], c1 = sBias[o+1];
        float* p0 = out + ((size_t)(b*64 + o))*HW + h*128;
        float* p1 = p0 + HW;
        p0[w0 + g]     = fmaxf((acc[nt][0] + c0)*i0 + a0, 0.f);
        p1[w0 + g]     = fmaxf((acc[nt][1] + c1)*i1 + a1, 0.f);
        p0[w0 + g + 8] = fmaxf((acc[nt][2] + c0)*i0 + a0, 0.f);
        p1[w0 + g + 8] = fmaxf((acc[nt][3] + c1)*i1 + a1, 0.f);
    }
}

// ---------------- host --------------------------------------------------------
extern "C" void kernel_launch(void* const* d_in, const int* in_sizes, int n_in,
                              void* d_out, int out_size)
{
    const float* x     = (const float*)d_in[0];
    const float* kern  = (const float*)d_in[1];
    const float* mw    = (const float*)d_in[2];
    const float* mb    = (const float*)d_in[3];
    const float* cow   = (const float*)d_in[4];
    const float* cob   = (const float*)d_in[5];
    const float* gamma = (const float*)d_in[6];
    const float* beta  = (const float*)d_in[7];
    const float* mean  = (const float*)d_in[8];
    const float* var   = (const float*)d_in[9];
    float* out   = (float*)d_out;
    float* masks = out + 4*64*HW;

    const int SMEM = 110592;
    static int configured = 0;
    cudaFuncSetAttribute(branch_mma, cudaFuncAttributeMaxDynamicSharedMemorySize, SMEM);
    cudaFuncSetAttribute(out_mma,    cudaFuncAttributeMaxDynamicSharedMemorySize, SMEM);
    (void)configured;

    mask_kernel<<<256, 256>>>(x, mw, mb, masks);
    xmT_kernel<<<1536, 256>>>(x, masks);
    wprep_kernel<<<1728, 256>>>(kern, cow);
    branch_mma<<<2048, 256, SMEM>>>();
    out_mma<<<512, 256, SMEM>>>(cob, gamma, beta, mean, var, out);
}